// round 16
// baseline (speedup 1.0000x reference)
#include <cuda_runtime.h>
#include <cuda_bf16.h>
#include <cstdint>
#include <math.h>

#define DIM 128
#define NCLUST 512
#define TOPK 8
#define PPART 64
#define NMAX 262144
#define COS_EPS 1e-8f
#define GAP_EPS 1e-5f

#define BM 64
#define BN 128
#define SSTR 136
#define NCHUNK 8

// ---------------- scratch ----------------
__device__ __nv_bfloat16 g_dhi[NCLUST * DIM];
__device__ __nv_bfloat16 g_dlo[NCLUST * DIM];
__device__ float g_dn[NCLUST];
__device__ float g_invdn[NCLUST];
__device__ float g_xinv[NMAX];
__device__ float g_csize[PPART * NCLUST];
__device__ float g_isum[(size_t)PPART * NCLUST * DIM];

__device__ __forceinline__ uint32_t bf2_u32(__nv_bfloat162 v) {
    return *reinterpret_cast<uint32_t*>(&v);
}

// ---------------- kernel: x row inverse norms (chunked) ----------------
__global__ __launch_bounds__(256)
void xnorm_kernel(const float* __restrict__ x, int rowOff) {
    const int l = threadIdx.x & 31;
    const int w = threadIdx.x >> 5;
    const size_t row = (size_t)rowOff + (size_t)blockIdx.x * 8 + w;
    float4 v = *(const float4*)(x + row * DIM + l * 4);
    float sq = v.x * v.x + v.y * v.y + v.z * v.z + v.w * v.w;
#pragma unroll
    for (int o = 16; o; o >>= 1) sq += __shfl_xor_sync(0xffffffffu, sq, o);
    if (l == 0) g_xinv[row] = 1.0f / fmaxf(sqrtf(sq), COS_EPS);
}

// ---------------- kernel: dict norms + hi/lo split ----------------
__global__ void prep_kernel(const float* __restrict__ dict) {
    int c = blockIdx.x;
    int d = threadIdx.x;
    __shared__ double red[DIM];
    float v = dict[c * DIM + d];
    red[d] = (double)v * (double)v;
    __syncthreads();
#pragma unroll
    for (int s = 64; s > 0; s >>= 1) {
        if (d < s) red[d] += red[d + s];
        __syncthreads();
    }
    __nv_bfloat16 hi = __float2bfloat16(v);
    g_dhi[c * DIM + d] = hi;
    g_dlo[c * DIM + d] = __float2bfloat16(v - __bfloat162float(hi));
    if (d == 0) {
        float dn = fmaxf(sqrtf((float)red[0]), COS_EPS);
        g_dn[c] = dn;
        g_invdn[c] = 1.0f / dn;
    }
}

// ---------------- mma / ldmatrix helpers ----------------
__device__ __forceinline__ void mma16816(float* d, uint32_t a0, uint32_t a1, uint32_t a2, uint32_t a3,
                                         uint32_t b0, uint32_t b1) {
    asm volatile("mma.sync.aligned.m16n8k16.row.col.f32.bf16.bf16.f32 "
                 "{%0,%1,%2,%3},{%4,%5,%6,%7},{%8,%9},{%0,%1,%2,%3};"
                 : "+f"(d[0]), "+f"(d[1]), "+f"(d[2]), "+f"(d[3])
                 : "r"(a0), "r"(a1), "r"(a2), "r"(a3), "r"(b0), "r"(b1));
}
__device__ __forceinline__ void ldmx4(uint32_t* r, const __nv_bfloat16* p) {
    uint32_t a = (uint32_t)__cvta_generic_to_shared(p);
    asm volatile("ldmatrix.sync.aligned.m8n8.x4.shared.b16 {%0,%1,%2,%3}, [%4];"
                 : "=r"(r[0]), "=r"(r[1]), "=r"(r[2]), "=r"(r[3]) : "r"(a));
}

// ---------------- kernel: distances GEMM (bf16x3, R13 config) ----------------
__global__ __launch_bounds__(256, 2)
void gemm_bf16x3(const float* __restrict__ x, float* __restrict__ dist, int rowOff) {
    extern __shared__ __nv_bfloat16 smh[];
    __nv_bfloat16* Ahi = smh;
    __nv_bfloat16* Alo = Ahi + BM * SSTR;
    __nv_bfloat16* Bhi = Alo + BM * SSTR;
    __nv_bfloat16* Blo = Bhi + BN * SSTR;
    __shared__ float srinv[BM];
    __shared__ float ssinv[BN];

    const int t = threadIdx.x;
    const int l = t & 31;
    const int wid = t >> 5;
    const int rowBase = rowOff + blockIdx.y * BM;
    const int colBase = blockIdx.x * BN;

    if (t < BN) ssinv[t] = g_invdn[colBase + t];
    if (t < BM) srinv[t] = g_xinv[rowBase + t];

    const float4* xb = (const float4*)(x + (size_t)rowBase * DIM);
#pragma unroll
    for (int i = 0; i < 8; ++i) {
        int flat = i * 256 + t;
        int r = flat >> 5, c4 = flat & 31;
        float4 v = xb[flat];
        __nv_bfloat162 h01 = __floats2bfloat162_rn(v.x, v.y);
        __nv_bfloat162 h23 = __floats2bfloat162_rn(v.z, v.w);
        __nv_bfloat162 l01 = __floats2bfloat162_rn(v.x - __bfloat162float(h01.x),
                                                   v.y - __bfloat162float(h01.y));
        __nv_bfloat162 l23 = __floats2bfloat162_rn(v.z - __bfloat162float(h23.x),
                                                   v.w - __bfloat162float(h23.y));
        __nv_bfloat16* ah = Ahi + r * SSTR + c4 * 4;
        __nv_bfloat16* al = Alo + r * SSTR + c4 * 4;
        *(__nv_bfloat162*)(ah) = h01;
        *(__nv_bfloat162*)(ah + 2) = h23;
        *(__nv_bfloat162*)(al) = l01;
        *(__nv_bfloat162*)(al + 2) = l23;
    }
    {
        const uint4* bh = (const uint4*)(g_dhi + (size_t)colBase * DIM);
        const uint4* bl = (const uint4*)(g_dlo + (size_t)colBase * DIM);
#pragma unroll
        for (int i = 0; i < 8; ++i) {
            int flat = i * 256 + t;
            int r = flat >> 4, h8 = flat & 15;
            *(uint4*)(Bhi + r * SSTR + h8 * 8) = bh[flat];
            *(uint4*)(Blo + r * SSTR + h8 * 8) = bl[flat];
        }
    }
    __syncthreads();

    const int wm = (wid >> 2) * 32;
    const int wn = (wid & 3) * 32;
    const int g = l >> 2;
    const int tg = l & 3;
    const int lrow = l & 15;
    const int lk8 = l >> 4;

    float acc[2][4][4];
#pragma unroll
    for (int m = 0; m < 2; ++m)
#pragma unroll
        for (int n = 0; n < 4; ++n)
#pragma unroll
            for (int j = 0; j < 4; ++j) acc[m][n][j] = 0.0f;

#pragma unroll
    for (int ks = 0; ks < 8; ++ks) {
        const int k = ks * 16;
        uint32_t ah[2][4], al[2][4];
#pragma unroll
        for (int m = 0; m < 2; ++m) {
            int off = (wm + m * 16 + lrow) * SSTR + k + lk8 * 8;
            ldmx4(ah[m], Ahi + off);
            ldmx4(al[m], Alo + off);
        }
#pragma unroll
        for (int nt = 0; nt < 2; ++nt) {
            uint32_t bh[4], bl[4];
            int off = (wn + nt * 16 + lrow) * SSTR + k + lk8 * 8;
            ldmx4(bh, Bhi + off);
            ldmx4(bl, Blo + off);
#pragma unroll
            for (int m = 0; m < 2; ++m) {
#pragma unroll
                for (int s = 0; s < 2; ++s) {
                    int n = nt * 2 + s;
                    mma16816(acc[m][n], ah[m][0], ah[m][1], ah[m][2], ah[m][3], bh[s], bh[s + 2]);
                    mma16816(acc[m][n], ah[m][0], ah[m][1], ah[m][2], ah[m][3], bl[s], bl[s + 2]);
                    mma16816(acc[m][n], al[m][0], al[m][1], al[m][2], al[m][3], bh[s], bh[s + 2]);
                }
            }
        }
    }

#pragma unroll
    for (int m = 0; m < 2; ++m) {
#pragma unroll
        for (int n = 0; n < 4; ++n) {
            int r0 = wm + m * 16 + g;
            int c0 = wn + n * 8 + 2 * tg;
            float ri0 = srinv[r0], ri1 = srinv[r0 + 8];
            float s0 = ssinv[c0], s1 = ssinv[c0 + 1];
            size_t base0 = (size_t)(rowBase + r0) * NCLUST + colBase + c0;
            float2 o0 = make_float2(acc[m][n][0] * ri0 * s0, acc[m][n][1] * ri0 * s1);
            float2 o1 = make_float2(acc[m][n][2] * ri1 * s0, acc[m][n][3] * ri1 * s1);
            *(float2*)(dist + base0) = o0;
            *(float2*)(dist + base0 + 8 * NCLUST) = o1;
        }
    }
}

// ---------------- topk helpers ----------------
__device__ __forceinline__ uint64_t packkey(float v, uint32_t low) {
    uint32_t u = __float_as_uint(v);
    u ^= ((uint32_t)((int)u >> 31)) | 0x80000000u;
    return ((uint64_t)u << 32) | low;
}
__device__ __forceinline__ float unpackval(uint64_t k) {
    uint32_t o = (uint32_t)(k >> 32);
    uint32_t u = (o & 0x80000000u) ? (o & 0x7FFFFFFFu) : ~o;
    return __uint_as_float(u);
}
__device__ __forceinline__ uint64_t warpmax64(uint64_t v) {
#pragma unroll
    for (int o = 16; o; o >>= 1) {
        uint64_t ov = __shfl_xor_sync(0xffffffffu, v, o);
        if (ov > v) v = ov;
    }
    return v;
}
__device__ __forceinline__ void red4(float* ptr, float a, float b, float c, float d) {
    asm volatile("red.global.add.v4.f32 [%0], {%1,%2,%3,%4};"
                 :: "l"(ptr), "f"(a), "f"(b), "f"(c), "f"(d) : "memory");
}

// ---------------- kernel: gap-gated topk (R13 config) ----------------
__global__ __launch_bounds__(256, 4)
void topk_kernel(const float* __restrict__ dist, const float* __restrict__ x,
                 const float* __restrict__ dict, float* __restrict__ ge,
                 float* __restrict__ idxo, int rowOff) {
    __shared__ uint64_t skeys[8][32];
    __shared__ float sxrow[8][128];
    const int t = threadIdx.x;
    const int l = t & 31;
    const int w = t >> 5;
    const size_t row = (size_t)rowOff + (size_t)blockIdx.x * 8 + w;
    float* xs = sxrow[w];

    float4 xv = *(const float4*)(x + row * DIM + l * 4);
    *(float4*)(xs + l * 4) = xv;

    const float* drow = dist + row * NCLUST;

    // pass 1: lane max
    float lm = -3.402823466e38f;
#pragma unroll
    for (int c = 0; c < 4; ++c) {
        float4 v = *(const float4*)(drow + c * 128 + l * 4);
        lm = fmaxf(lm, fmaxf(fmaxf(v.x, v.y), fmaxf(v.z, v.w)));
    }

    // bitonic ascending sort of lane maxima; tau9 from lane 23
    float bv = lm;
#pragma unroll
    for (int k = 2; k <= 32; k <<= 1) {
#pragma unroll
        for (int j = k >> 1; j; j >>= 1) {
            float ov = __shfl_xor_sync(0xffffffffu, bv, j);
            bool dir = ((l & k) == 0);
            bool lower = ((l & j) == 0);
            bv = (dir == lower) ? fminf(bv, ov) : fmaxf(bv, ov);
        }
    }
    const float tauM = __shfl_sync(0xffffffffu, bv, 23) - GAP_EPS;

    // pass 2: ballot-compaction (L1 re-read)
    int nc = 0;
#pragma unroll
    for (int c = 0; c < 4; ++c) {
        float4 v = *(const float4*)(drow + c * 128 + l * 4);
#pragma unroll
        for (int q = 0; q < 4; ++q) {
            float val = (q == 0) ? v.x : (q == 1) ? v.y : (q == 2) ? v.z : v.w;
            bool p = (val >= tauM);
            unsigned mk = __ballot_sync(0xffffffffu, p);
            if (p) {
                int pos = nc + __popc(mk & ((1u << l) - 1u));
                if (pos < 32) skeys[w][pos] = packkey(val, 511u - (uint32_t)(c * 128 + l * 4 + q));
            }
            nc += __popc(mk);
        }
    }
    const int ncs = (nc < 32) ? nc : 32;
    __syncwarp();

    uint64_t key = (l < ncs) ? skeys[w][l] : 0ULL;
#pragma unroll
    for (int k = 2; k <= 32; k <<= 1) {
#pragma unroll
        for (int j = k >> 1; j; j >>= 1) {
            uint64_t ov = __shfl_xor_sync(0xffffffffu, key, j);
            bool dir = ((l & k) == 0);
            bool lower = ((l & j) == 0);
            bool takeMin = (dir == lower);
            key = takeMin ? ((ov < key) ? ov : key) : ((ov > key) ? ov : key);
        }
    }

    float tv9[9]; int ti9[9];
#pragma unroll
    for (int r = 0; r < 9; ++r) {
        uint64_t kk = __shfl_sync(0xffffffffu, key, 31 - r);
        tv9[r] = unpackval(kk);
        ti9[r] = 511 - (int)((uint32_t)kk & 0x1FFu);
    }
    float gapmin = tv9[0] - tv9[1];
#pragma unroll
    for (int r = 1; r < 8; ++r) gapmin = fminf(gapmin, tv9[r] - tv9[r + 1]);

    const bool fb = (gapmin < GAP_EPS) || (nc > 32);

    float tv[8]; int ti[8];
    if (!fb) {
#pragma unroll
        for (int r = 0; r < 8; ++r) { tv[r] = tv9[r]; ti[r] = ti9[r]; }
    } else {
        double s = (double)xv.x * xv.x + (double)xv.y * xv.y +
                   (double)xv.z * xv.z + (double)xv.w * xv.w;
#pragma unroll
        for (int o = 16; o; o >>= 1) s += __shfl_xor_sync(0xffffffffu, s, o);
        const float xn = fmaxf(sqrtf((float)s), COS_EPS);

        uint64_t qkey = 0ULL;
        if (l < ncs) {
            const int ci = 511 - (int)((uint32_t)skeys[w][l] & 0x1FFu);
            const float4* dr4 = (const float4*)(dict + (size_t)ci * DIM);
            float p = 0.0f;
#pragma unroll
            for (int k4 = 0; k4 < 32; ++k4) {
                float4 xq = *(const float4*)(xs + k4 * 4);
                float4 dq = dr4[k4];
                p = fmaf(xq.x, dq.x, p);
                p = fmaf(xq.y, dq.y, p);
                p = fmaf(xq.z, dq.z, p);
                p = fmaf(xq.w, dq.w, p);
            }
            float q = __fdiv_rn(p, __fmul_rn(xn, g_dn[ci]));
            qkey = packkey(q, (uint32_t)(511 - ci));
        }
#pragma unroll
        for (int r = 0; r < 8; ++r) {
            uint64_t mm = warpmax64(qkey);
            tv[r] = unpackval(mm);
            ti[r] = 511 - (int)((uint32_t)mm & 0x1FFu);
            if (qkey == mm) qkey = 0ULL;
        }
    }

    // softmaxes: e = exp(d), e2 = e^20 via squarings
    const float mx = tv[0];
    float e[8], e2[8], se = 0.f, se2 = 0.f;
#pragma unroll
    for (int k = 0; k < 8; ++k) {
        e[k] = __expf(tv[k] - mx);
        se += e[k];
        float p2 = e[k] * e[k];
        float p4 = p2 * p2;
        float p16 = p4 * p4;
        p16 = p16 * p16;
        e2[k] = p16 * p4;
        se2 += e2[k];
    }
    float wgt[8], ew[8];
#pragma unroll
    for (int k = 0; k < 8; ++k) { wgt[k] = e[k] / se; ew[k] = e2[k] / se2; }

    float4 g = make_float4(0.f, 0.f, 0.f, 0.f);
#pragma unroll
    for (int k = 0; k < 8; ++k) {
        float4 dv = *(const float4*)(dict + (size_t)ti[k] * DIM + l * 4);
        g.x += wgt[k] * dv.x; g.y += wgt[k] * dv.y;
        g.z += wgt[k] * dv.z; g.w += wgt[k] * dv.w;
    }
    *(float4*)(ge + row * DIM + l * 4) = g;

    if (l == 0) {
        float4 u0 = make_float4((float)ti[0], (float)ti[1], (float)ti[2], (float)ti[3]);
        float4 u1 = make_float4((float)ti[4], (float)ti[5], (float)ti[6], (float)ti[7]);
        *(float4*)(idxo + row * TOPK) = u0;
        *(float4*)(idxo + row * TOPK + 4) = u1;
    }

    const int pp = (int)(blockIdx.x & (PPART - 1));
    if (l < 8) {
        int myti = ti[0]; float myw = ew[0];
#pragma unroll
        for (int k = 1; k < 8; ++k) { if (l == k) { myti = ti[k]; myw = ew[k]; } }
        atomicAdd(g_csize + pp * NCLUST + myti, myw);
    }
#pragma unroll
    for (int k = 0; k < 8; ++k) {
        float sc = ew[k];
        float* ptr = g_isum + ((size_t)pp * NCLUST + (size_t)ti[k]) * DIM + l * 4;
        red4(ptr, sc * xv.x, sc * xv.y, sc * xv.z, sc * xv.w);
    }
}

// ---------------- kernel: finalize EMA dictionary ----------------
__global__ void finalize_kernel(const float* __restrict__ dict, float* __restrict__ ndict) {
    int c = blockIdx.x;
    int d = threadIdx.x;
    float cs = 0.f;
#pragma unroll 8
    for (int p = 0; p < PPART; ++p) cs += g_csize[p * NCLUST + c];
    float s = 0.f;
#pragma unroll 8
    for (int p = 0; p < PPART; ++p) s += g_isum[((size_t)p * NCLUST + c) * DIM + d];
    float dv = dict[c * DIM + d];
    float nv = (cs != 0.0f) ? (dv * 0.1f + (s / cs) * 0.9f) : dv;
    ndict[c * DIM + d] = nv;
}

// ---------------- launch: 2-stream pipelined chunks, xnorm interleaved ----------------
extern "C" void kernel_launch(void* const* d_in, const int* in_sizes, int n_in,
                              void* d_out, int out_size) {
    const float* x = (const float*)d_in[0];
    const float* dict = (const float*)d_in[1];
    const size_t N = (size_t)in_sizes[0] / DIM;

    float* out = (float*)d_out;
    float* ge    = out;
    float* idxo  = ge + N * DIM;
    float* dist  = idxo + N * TOPK;
    float* ndict = dist + N * NCLUST;

    static cudaStream_t s2 = nullptr;
    static cudaEvent_t evP = nullptr, evG[NCHUNK];
    if (s2 == nullptr) {
        cudaStreamCreateWithFlags(&s2, cudaStreamNonBlocking);
        cudaEventCreateWithFlags(&evP, cudaEventDisableTiming);
        for (int c = 0; c < NCHUNK; ++c)
            cudaEventCreateWithFlags(&evG[c], cudaEventDisableTiming);
    }

    void* pcs = nullptr; void* pis = nullptr;
    cudaGetSymbolAddress(&pcs, g_csize);
    cudaGetSymbolAddress(&pis, g_isum);
    cudaMemsetAsync(pcs, 0, sizeof(float) * PPART * NCLUST);
    cudaMemsetAsync(pis, 0, sizeof(float) * (size_t)PPART * NCLUST * DIM);

    prep_kernel<<<NCLUST, DIM>>>(dict);
    cudaEventRecord(evP, 0);
    cudaStreamWaitEvent(s2, evP, 0);

    const int gsmem = (2 * BM + 2 * BN) * SSTR * (int)sizeof(__nv_bfloat16);
    cudaFuncSetAttribute(gemm_bf16x3, cudaFuncAttributeMaxDynamicSharedMemorySize, gsmem);

    const int chunkRows = (int)(N / NCHUNK);
    dim3 ggrid(NCLUST / BN, (unsigned)(chunkRows / BM));
    const unsigned tgrid = (unsigned)(chunkRows / 8);
    const unsigned xgrid = (unsigned)(chunkRows / 8);

    for (int c = 0; c < NCHUNK; ++c) {
        xnorm_kernel<<<xgrid, 256, 0, s2>>>(x, c * chunkRows);
        gemm_bf16x3<<<ggrid, 256, gsmem, s2>>>(x, dist, c * chunkRows);
        cudaEventRecord(evG[c], s2);
    }
    for (int c = 0; c < NCHUNK; ++c) {
        cudaStreamWaitEvent(0, evG[c], 0);
        topk_kernel<<<tgrid, 256>>>(dist, x, dict, ge, idxo, c * chunkRows);
    }

    finalize_kernel<<<NCLUST, DIM>>>(dict, ndict);
}

// round 17
// speedup vs baseline: 1.0566x; 1.0566x over previous
#include <cuda_runtime.h>
#include <cuda_bf16.h>
#include <cstdint>
#include <math.h>

#define DIM 128
#define NCLUST 512
#define TOPK 8
#define PPART 64
#define NMAX 262144
#define COS_EPS 1e-8f
#define GAP_EPS 1e-5f

#define BM 64
#define BN 128
#define SSTR 136
#define NCHUNK 8

// ---------------- scratch ----------------
__device__ __nv_bfloat16 g_dhi[NCLUST * DIM];
__device__ __nv_bfloat16 g_dlo[NCLUST * DIM];
__device__ float g_dn[NCLUST];
__device__ float g_invdn[NCLUST];
__device__ float g_xinv[NMAX];
__device__ float g_csize[PPART * NCLUST];
__device__ float g_isum[(size_t)PPART * NCLUST * DIM];

__device__ __forceinline__ uint32_t bf2_u32(__nv_bfloat162 v) {
    return *reinterpret_cast<uint32_t*>(&v);
}

// ---------------- kernel: x row inverse norms ----------------
__global__ __launch_bounds__(256)
void xnorm_kernel(const float* __restrict__ x) {
    const int l = threadIdx.x & 31;
    const int w = threadIdx.x >> 5;
    const size_t row = (size_t)blockIdx.x * 8 + w;
    float4 v = *(const float4*)(x + row * DIM + l * 4);
    float sq = v.x * v.x + v.y * v.y + v.z * v.z + v.w * v.w;
#pragma unroll
    for (int o = 16; o; o >>= 1) sq += __shfl_xor_sync(0xffffffffu, sq, o);
    if (l == 0) g_xinv[row] = 1.0f / fmaxf(sqrtf(sq), COS_EPS);
}

// ---------------- kernel: dict norms + hi/lo split ----------------
__global__ void prep_kernel(const float* __restrict__ dict) {
    int c = blockIdx.x;
    int d = threadIdx.x;
    __shared__ double red[DIM];
    float v = dict[c * DIM + d];
    red[d] = (double)v * (double)v;
    __syncthreads();
#pragma unroll
    for (int s = 64; s > 0; s >>= 1) {
        if (d < s) red[d] += red[d + s];
        __syncthreads();
    }
    __nv_bfloat16 hi = __float2bfloat16(v);
    g_dhi[c * DIM + d] = hi;
    g_dlo[c * DIM + d] = __float2bfloat16(v - __bfloat162float(hi));
    if (d == 0) {
        float dn = fmaxf(sqrtf((float)red[0]), COS_EPS);
        g_dn[c] = dn;
        g_invdn[c] = 1.0f / dn;
    }
}

// ---------------- mma / ldmatrix helpers ----------------
__device__ __forceinline__ void mma16816(float* d, uint32_t a0, uint32_t a1, uint32_t a2, uint32_t a3,
                                         uint32_t b0, uint32_t b1) {
    asm volatile("mma.sync.aligned.m16n8k16.row.col.f32.bf16.bf16.f32 "
                 "{%0,%1,%2,%3},{%4,%5,%6,%7},{%8,%9},{%0,%1,%2,%3};"
                 : "+f"(d[0]), "+f"(d[1]), "+f"(d[2]), "+f"(d[3])
                 : "r"(a0), "r"(a1), "r"(a2), "r"(a3), "r"(b0), "r"(b1));
}
__device__ __forceinline__ void ldmx4(uint32_t* r, const __nv_bfloat16* p) {
    uint32_t a = (uint32_t)__cvta_generic_to_shared(p);
    asm volatile("ldmatrix.sync.aligned.m8n8.x4.shared.b16 {%0,%1,%2,%3}, [%4];"
                 : "=r"(r[0]), "=r"(r[1]), "=r"(r[2]), "=r"(r[3]) : "r"(a));
}

// ---------------- kernel: distances GEMM (bf16x3) ----------------
__global__ __launch_bounds__(256, 2)
void gemm_bf16x3(const float* __restrict__ x, float* __restrict__ dist, int rowOff) {
    extern __shared__ __nv_bfloat16 smh[];
    __nv_bfloat16* Ahi = smh;
    __nv_bfloat16* Alo = Ahi + BM * SSTR;
    __nv_bfloat16* Bhi = Alo + BM * SSTR;
    __nv_bfloat16* Blo = Bhi + BN * SSTR;
    __shared__ float srinv[BM];
    __shared__ float ssinv[BN];

    const int t = threadIdx.x;
    const int l = t & 31;
    const int wid = t >> 5;
    const int rowBase = rowOff + blockIdx.y * BM;
    const int colBase = blockIdx.x * BN;

    if (t < BN) ssinv[t] = g_invdn[colBase + t];
    if (t < BM) srinv[t] = g_xinv[rowBase + t];

    const float4* xb = (const float4*)(x + (size_t)rowBase * DIM);
#pragma unroll
    for (int i = 0; i < 8; ++i) {
        int flat = i * 256 + t;
        int r = flat >> 5, c4 = flat & 31;
        float4 v = xb[flat];
        __nv_bfloat162 h01 = __floats2bfloat162_rn(v.x, v.y);
        __nv_bfloat162 h23 = __floats2bfloat162_rn(v.z, v.w);
        __nv_bfloat162 l01 = __floats2bfloat162_rn(v.x - __bfloat162float(h01.x),
                                                   v.y - __bfloat162float(h01.y));
        __nv_bfloat162 l23 = __floats2bfloat162_rn(v.z - __bfloat162float(h23.x),
                                                   v.w - __bfloat162float(h23.y));
        __nv_bfloat16* ah = Ahi + r * SSTR + c4 * 4;
        __nv_bfloat16* al = Alo + r * SSTR + c4 * 4;
        *(__nv_bfloat162*)(ah) = h01;
        *(__nv_bfloat162*)(ah + 2) = h23;
        *(__nv_bfloat162*)(al) = l01;
        *(__nv_bfloat162*)(al + 2) = l23;
    }
    {
        const uint4* bh = (const uint4*)(g_dhi + (size_t)colBase * DIM);
        const uint4* bl = (const uint4*)(g_dlo + (size_t)colBase * DIM);
#pragma unroll
        for (int i = 0; i < 8; ++i) {
            int flat = i * 256 + t;
            int r = flat >> 4, h8 = flat & 15;
            *(uint4*)(Bhi + r * SSTR + h8 * 8) = bh[flat];
            *(uint4*)(Blo + r * SSTR + h8 * 8) = bl[flat];
        }
    }
    __syncthreads();

    const int wm = (wid >> 2) * 32;
    const int wn = (wid & 3) * 32;
    const int g = l >> 2;
    const int tg = l & 3;
    const int lrow = l & 15;
    const int lk8 = l >> 4;

    float acc[2][4][4];
#pragma unroll
    for (int m = 0; m < 2; ++m)
#pragma unroll
        for (int n = 0; n < 4; ++n)
#pragma unroll
            for (int j = 0; j < 4; ++j) acc[m][n][j] = 0.0f;

#pragma unroll
    for (int ks = 0; ks < 8; ++ks) {
        const int k = ks * 16;
        uint32_t ah[2][4], al[2][4];
#pragma unroll
        for (int m = 0; m < 2; ++m) {
            int off = (wm + m * 16 + lrow) * SSTR + k + lk8 * 8;
            ldmx4(ah[m], Ahi + off);
            ldmx4(al[m], Alo + off);
        }
#pragma unroll
        for (int nt = 0; nt < 2; ++nt) {
            uint32_t bh[4], bl[4];
            int off = (wn + nt * 16 + lrow) * SSTR + k + lk8 * 8;
            ldmx4(bh, Bhi + off);
            ldmx4(bl, Blo + off);
#pragma unroll
            for (int m = 0; m < 2; ++m) {
#pragma unroll
                for (int s = 0; s < 2; ++s) {
                    int n = nt * 2 + s;
                    mma16816(acc[m][n], ah[m][0], ah[m][1], ah[m][2], ah[m][3], bh[s], bh[s + 2]);
                    mma16816(acc[m][n], ah[m][0], ah[m][1], ah[m][2], ah[m][3], bl[s], bl[s + 2]);
                    mma16816(acc[m][n], al[m][0], al[m][1], al[m][2], al[m][3], bh[s], bh[s + 2]);
                }
            }
        }
    }

#pragma unroll
    for (int m = 0; m < 2; ++m) {
#pragma unroll
        for (int n = 0; n < 4; ++n) {
            int r0 = wm + m * 16 + g;
            int c0 = wn + n * 8 + 2 * tg;
            float ri0 = srinv[r0], ri1 = srinv[r0 + 8];
            float s0 = ssinv[c0], s1 = ssinv[c0 + 1];
            size_t base0 = (size_t)(rowBase + r0) * NCLUST + colBase + c0;
            float2 o0 = make_float2(acc[m][n][0] * ri0 * s0, acc[m][n][1] * ri0 * s1);
            float2 o1 = make_float2(acc[m][n][2] * ri1 * s0, acc[m][n][3] * ri1 * s1);
            *(float2*)(dist + base0) = o0;
            *(float2*)(dist + base0 + 8 * NCLUST) = o1;
        }
    }
}

// ---------------- topk helpers ----------------
__device__ __forceinline__ uint64_t packkey(float v, uint32_t low) {
    uint32_t u = __float_as_uint(v);
    u ^= ((uint32_t)((int)u >> 31)) | 0x80000000u;
    return ((uint64_t)u << 32) | low;
}
__device__ __forceinline__ float unpackval(uint64_t k) {
    uint32_t o = (uint32_t)(k >> 32);
    uint32_t u = (o & 0x80000000u) ? (o & 0x7FFFFFFFu) : ~o;
    return __uint_as_float(u);
}
__device__ __forceinline__ uint64_t warpmax64(uint64_t v) {
#pragma unroll
    for (int o = 16; o; o >>= 1) {
        uint64_t ov = __shfl_xor_sync(0xffffffffu, v, o);
        if (ov > v) v = ov;
    }
    return v;
}
__device__ __forceinline__ void red4(float* ptr, float a, float b, float c, float d) {
    asm volatile("red.global.add.v4.f32 [%0], {%1,%2,%3,%4};"
                 :: "l"(ptr), "f"(a), "f"(b), "f"(c), "f"(d) : "memory");
}

// ---------------- kernel: gap-gated topk ----------------
__global__ __launch_bounds__(256, 4)
void topk_kernel(const float* __restrict__ dist, const float* __restrict__ x,
                 const float* __restrict__ dict, float* __restrict__ ge,
                 float* __restrict__ idxo, int rowOff) {
    __shared__ uint64_t skeys[8][32];
    __shared__ float sxrow[8][128];
    const int t = threadIdx.x;
    const int l = t & 31;
    const int w = t >> 5;
    const size_t row = (size_t)rowOff + (size_t)blockIdx.x * 8 + w;
    float* xs = sxrow[w];

    float4 xv = *(const float4*)(x + row * DIM + l * 4);
    *(float4*)(xs + l * 4) = xv;

    const float* drow = dist + row * NCLUST;

    // pass 1: lane max
    float lm = -3.402823466e38f;
#pragma unroll
    for (int c = 0; c < 4; ++c) {
        float4 v = *(const float4*)(drow + c * 128 + l * 4);
        lm = fmaxf(lm, fmaxf(fmaxf(v.x, v.y), fmaxf(v.z, v.w)));
    }

    // bitonic ascending sort of lane maxima; tau9 from lane 23
    float bv = lm;
#pragma unroll
    for (int k = 2; k <= 32; k <<= 1) {
#pragma unroll
        for (int j = k >> 1; j; j >>= 1) {
            float ov = __shfl_xor_sync(0xffffffffu, bv, j);
            bool dir = ((l & k) == 0);
            bool lower = ((l & j) == 0);
            bv = (dir == lower) ? fminf(bv, ov) : fmaxf(bv, ov);
        }
    }
    const float tauM = __shfl_sync(0xffffffffu, bv, 23) - GAP_EPS;

    // pass 2: ballot-compaction (L1 re-read)
    int nc = 0;
#pragma unroll
    for (int c = 0; c < 4; ++c) {
        float4 v = *(const float4*)(drow + c * 128 + l * 4);
#pragma unroll
        for (int q = 0; q < 4; ++q) {
            float val = (q == 0) ? v.x : (q == 1) ? v.y : (q == 2) ? v.z : v.w;
            bool p = (val >= tauM);
            unsigned mk = __ballot_sync(0xffffffffu, p);
            if (p) {
                int pos = nc + __popc(mk & ((1u << l) - 1u));
                if (pos < 32) skeys[w][pos] = packkey(val, 511u - (uint32_t)(c * 128 + l * 4 + q));
            }
            nc += __popc(mk);
        }
    }
    const int ncs = (nc < 32) ? nc : 32;
    __syncwarp();

    uint64_t key = (l < ncs) ? skeys[w][l] : 0ULL;
#pragma unroll
    for (int k = 2; k <= 32; k <<= 1) {
#pragma unroll
        for (int j = k >> 1; j; j >>= 1) {
            uint64_t ov = __shfl_xor_sync(0xffffffffu, key, j);
            bool dir = ((l & k) == 0);
            bool lower = ((l & j) == 0);
            bool takeMin = (dir == lower);
            key = takeMin ? ((ov < key) ? ov : key) : ((ov > key) ? ov : key);
        }
    }

    float tv9[9]; int ti9[9];
#pragma unroll
    for (int r = 0; r < 9; ++r) {
        uint64_t kk = __shfl_sync(0xffffffffu, key, 31 - r);
        tv9[r] = unpackval(kk);
        ti9[r] = 511 - (int)((uint32_t)kk & 0x1FFu);
    }
    float gapmin = tv9[0] - tv9[1];
#pragma unroll
    for (int r = 1; r < 8; ++r) gapmin = fminf(gapmin, tv9[r] - tv9[r + 1]);

    const bool fb = (gapmin < GAP_EPS) || (nc > 32);

    float tv[8]; int ti[8];
    if (!fb) {
#pragma unroll
        for (int r = 0; r < 8; ++r) { tv[r] = tv9[r]; ti[r] = ti9[r]; }
    } else {
        double s = (double)xv.x * xv.x + (double)xv.y * xv.y +
                   (double)xv.z * xv.z + (double)xv.w * xv.w;
#pragma unroll
        for (int o = 16; o; o >>= 1) s += __shfl_xor_sync(0xffffffffu, s, o);
        const float xn = fmaxf(sqrtf((float)s), COS_EPS);

        uint64_t qkey = 0ULL;
        if (l < ncs) {
            const int ci = 511 - (int)((uint32_t)skeys[w][l] & 0x1FFu);
            const float4* dr4 = (const float4*)(dict + (size_t)ci * DIM);
            float p = 0.0f;
#pragma unroll
            for (int k4 = 0; k4 < 32; ++k4) {
                float4 xq = *(const float4*)(xs + k4 * 4);
                float4 dq = dr4[k4];
                p = fmaf(xq.x, dq.x, p);
                p = fmaf(xq.y, dq.y, p);
                p = fmaf(xq.z, dq.z, p);
                p = fmaf(xq.w, dq.w, p);
            }
            float q = __fdiv_rn(p, __fmul_rn(xn, g_dn[ci]));
            qkey = packkey(q, (uint32_t)(511 - ci));
        }
#pragma unroll
        for (int r = 0; r < 8; ++r) {
            uint64_t mm = warpmax64(qkey);
            tv[r] = unpackval(mm);
            ti[r] = 511 - (int)((uint32_t)mm & 0x1FFu);
            if (qkey == mm) qkey = 0ULL;
        }
    }

    // softmaxes
    const float mx = tv[0];
    float e[8], e2[8], se = 0.f, se2 = 0.f;
#pragma unroll
    for (int k = 0; k < 8; ++k) {
        e[k] = __expf(tv[k] - mx);            se += e[k];
        e2[k] = __expf(20.0f * (tv[k] - mx)); se2 += e2[k];
    }
    float wgt[8], ew[8];
#pragma unroll
    for (int k = 0; k < 8; ++k) { wgt[k] = e[k] / se; ew[k] = e2[k] / se2; }

    float4 g = make_float4(0.f, 0.f, 0.f, 0.f);
#pragma unroll
    for (int k = 0; k < 8; ++k) {
        float4 dv = *(const float4*)(dict + (size_t)ti[k] * DIM + l * 4);
        g.x += wgt[k] * dv.x; g.y += wgt[k] * dv.y;
        g.z += wgt[k] * dv.z; g.w += wgt[k] * dv.w;
    }
    *(float4*)(ge + row * DIM + l * 4) = g;

    if (l == 0) {
        float4 u0 = make_float4((float)ti[0], (float)ti[1], (float)ti[2], (float)ti[3]);
        float4 u1 = make_float4((float)ti[4], (float)ti[5], (float)ti[6], (float)ti[7]);
        *(float4*)(idxo + row * TOPK) = u0;
        *(float4*)(idxo + row * TOPK + 4) = u1;
    }

    const int pp = (int)(blockIdx.x & (PPART - 1));
    if (l < 8) {
        int myti = ti[0]; float myw = ew[0];
#pragma unroll
        for (int k = 1; k < 8; ++k) { if (l == k) { myti = ti[k]; myw = ew[k]; } }
        atomicAdd(g_csize + pp * NCLUST + myti, myw);
    }
#pragma unroll
    for (int k = 0; k < 8; ++k) {
        float sc = ew[k];
        float* ptr = g_isum + ((size_t)pp * NCLUST + (size_t)ti[k]) * DIM + l * 4;
        red4(ptr, sc * xv.x, sc * xv.y, sc * xv.z, sc * xv.w);
    }
}

// ---------------- kernel: finalize EMA dictionary ----------------
__global__ void finalize_kernel(const float* __restrict__ dict, float* __restrict__ ndict) {
    int c = blockIdx.x;
    int d = threadIdx.x;
    float cs = 0.f;
#pragma unroll 8
    for (int p = 0; p < PPART; ++p) cs += g_csize[p * NCLUST + c];
    float s = 0.f;
#pragma unroll 8
    for (int p = 0; p < PPART; ++p) s += g_isum[((size_t)p * NCLUST + c) * DIM + d];
    float dv = dict[c * DIM + d];
    float nv = (cs != 0.0f) ? (dv * 0.1f + (s / cs) * 0.9f) : dv;
    ndict[c * DIM + d] = nv;
}

// ---------------- launch ----------------
extern "C" void kernel_launch(void* const* d_in, const int* in_sizes, int n_in,
                              void* d_out, int out_size) {
    const float* x = (const float*)d_in[0];
    const float* dict = (const float*)d_in[1];
    const size_t N = (size_t)in_sizes[0] / DIM;

    float* out = (float*)d_out;
    float* ge    = out;
    float* idxo  = ge + N * DIM;
    float* dist  = idxo + N * TOPK;
    float* ndict = dist + N * NCLUST;

    static cudaStream_t s2 = nullptr;
    static cudaEvent_t evP = nullptr, evG[NCHUNK];
    if (s2 == nullptr) {
        cudaStreamCreateWithFlags(&s2, cudaStreamNonBlocking);
        cudaEventCreateWithFlags(&evP, cudaEventDisableTiming);
        for (int c = 0; c < NCHUNK; ++c)
            cudaEventCreateWithFlags(&evG[c], cudaEventDisableTiming);
    }

    void* pcs = nullptr; void* pis = nullptr;
    cudaGetSymbolAddress(&pcs, g_csize);
    cudaGetSymbolAddress(&pis, g_isum);
    cudaMemsetAsync(pcs, 0, sizeof(float) * PPART * NCLUST);
    cudaMemsetAsync(pis, 0, sizeof(float) * (size_t)PPART * NCLUST * DIM);

    // xnorm on s2 overlaps prep+memsets on stream 0
    xnorm_kernel<<<(unsigned)(N / 8), 256, 0, s2>>>(x);
    prep_kernel<<<NCLUST, DIM>>>(dict);
    cudaEventRecord(evP, 0);
    cudaStreamWaitEvent(s2, evP, 0);

    const int gsmem = (2 * BM + 2 * BN) * SSTR * (int)sizeof(__nv_bfloat16);
    cudaFuncSetAttribute(gemm_bf16x3, cudaFuncAttributeMaxDynamicSharedMemorySize, gsmem);

    const int chunkRows = (int)(N / NCHUNK);
    dim3 ggrid(NCLUST / BN, (unsigned)(chunkRows / BM));
    const unsigned tgrid = (unsigned)(chunkRows / 8);

    for (int c = 0; c < NCHUNK; ++c) {
        gemm_bf16x3<<<ggrid, 256, gsmem, s2>>>(x, dist, c * chunkRows);
        cudaEventRecord(evG[c], s2);
    }
    for (int c = 0; c < NCHUNK; ++c) {
        cudaStreamWaitEvent(0, evG[c], 0);
        topk_kernel<<<tgrid, 256>>>(dist, x, dict, ge, idxo, c * chunkRows);
    }

    finalize_kernel<<<NCLUST, DIM>>>(dict, ndict);
}